// round 5
// baseline (speedup 1.0000x reference)
#include <cuda_runtime.h>
#include <cuda_fp16.h>

// V=100000, K=32, F=64.
// out[v, 0:64]   = mean over K neighbours of x[idxs[v,k], :]
// out[v, 64:128] = max  over K neighbours
//
// Kernel 1: convert x fp32 -> fp16 scratch (row = 128B = one cache line).
// Kernel 2: warp per vertex; 8 lanes per gathered row (int4 = 8 fp16 per
//   lane), one LDG.128 gathers 4 neighbour rows. The 4 gathers of each
//   half-warp batch are fused into ONE asm volatile block so ptxas cannot
//   re-serialize them (R3/R4 showed it pins regs=32 and caps MLP at ~2).
//   Packed HADD2/HMAX2 accumulation, 2-step xor-butterfly.

#define KNN  32
#define FDIM 64
#define VMAX 100000

__device__ __align__(16) __half2 g_xh[VMAX * (FDIM / 2)];   // 12.8 MB

__global__ __launch_bounds__(256)
void convert_kernel(const float4* __restrict__ x4, int n8)   // n8 = V*F/8
{
    int i = blockIdx.x * blockDim.x + threadIdx.x;
    if (i < n8) {
        float4 a = x4[2 * i];
        float4 b = x4[2 * i + 1];
        __half2 h0 = __floats2half2_rn(a.x, a.y);
        __half2 h1 = __floats2half2_rn(a.z, a.w);
        __half2 h2 = __floats2half2_rn(b.x, b.y);
        __half2 h3 = __floats2half2_rn(b.z, b.w);
        int4 packed;
        packed.x = *(const int*)&h0;
        packed.y = *(const int*)&h1;
        packed.z = *(const int*)&h2;
        packed.w = *(const int*)&h3;
        *reinterpret_cast<int4*>(&g_xh[4 * i]) = packed;
    }
}

__device__ __forceinline__ __half2 h2_shfl_xor(__half2 v, int off)
{
    unsigned int u = *(const unsigned int*)&v;
    u = __shfl_xor_sync(0xffffffffu, u, off);
    return *(const __half2*)&u;
}

__global__ __launch_bounds__(256)
void knn_mean_max_kernel(const int* __restrict__ idxs,
                         float4*    __restrict__ out4,
                         int V)
{
    const int warp = (blockIdx.x * blockDim.x + threadIdx.x) >> 5;
    const int lane = threadIdx.x & 31;
    if (warp >= V) return;

    const int g = lane >> 3;   // which of 4 rows this lane helps gather
    const int p = lane & 7;    // 16B-chunk position within the 128B row

    // Coalesced index load: lane l holds idxs[warp][l]
    const int my_idx = idxs[warp * KNN + lane];

    const __half2 zero = __float2half2_rn(0.0f);
    const __half2 ninf = __float2half2_rn(-65504.0f);
    __half2 s0 = zero, s1 = zero, s2 = zero, s3 = zero;
    __half2 m0 = ninf, m1 = ninf, m2 = ninf, m3 = ninf;

    const char* __restrict__ xbase = (const char*)g_xh;

    #pragma unroll
    for (int half = 0; half < 2; ++half) {
        // Row indices for this batch (independent of each other).
        const int i0 = __shfl_sync(0xffffffffu, my_idx, half * 16 + 0 + g);
        const int i1 = __shfl_sync(0xffffffffu, my_idx, half * 16 + 4 + g);
        const int i2 = __shfl_sync(0xffffffffu, my_idx, half * 16 + 8 + g);
        const int i3 = __shfl_sync(0xffffffffu, my_idx, half * 16 + 12 + g);
        const char* p0 = xbase + ((long long)i0 * 128 + p * 16);
        const char* p1 = xbase + ((long long)i1 * 128 + p * 16);
        const char* p2 = xbase + ((long long)i2 * 128 + p * 16);
        const char* p3 = xbase + ((long long)i3 * 128 + p * 16);

        // ---- 4 gathers in ONE asm block: ptxas must keep MLP=4 ----
        unsigned int r0, r1, r2, r3, r4, r5, r6, r7;
        unsigned int r8, r9, r10, r11, r12, r13, r14, r15;
        asm volatile(
            "ld.global.nc.v4.u32 {%0,%1,%2,%3}, [%16];\n\t"
            "ld.global.nc.v4.u32 {%4,%5,%6,%7}, [%17];\n\t"
            "ld.global.nc.v4.u32 {%8,%9,%10,%11}, [%18];\n\t"
            "ld.global.nc.v4.u32 {%12,%13,%14,%15}, [%19];\n\t"
            : "=r"(r0), "=r"(r1), "=r"(r2), "=r"(r3),
              "=r"(r4), "=r"(r5), "=r"(r6), "=r"(r7),
              "=r"(r8), "=r"(r9), "=r"(r10), "=r"(r11),
              "=r"(r12), "=r"(r13), "=r"(r14), "=r"(r15)
            : "l"(p0), "l"(p1), "l"(p2), "l"(p3));

        const __half2 a0 = *(const __half2*)&r0,  a1 = *(const __half2*)&r1;
        const __half2 a2 = *(const __half2*)&r2,  a3 = *(const __half2*)&r3;
        const __half2 b0 = *(const __half2*)&r4,  b1 = *(const __half2*)&r5;
        const __half2 b2 = *(const __half2*)&r6,  b3 = *(const __half2*)&r7;
        const __half2 c0 = *(const __half2*)&r8,  c1 = *(const __half2*)&r9;
        const __half2 c2 = *(const __half2*)&r10, c3 = *(const __half2*)&r11;
        const __half2 d0 = *(const __half2*)&r12, d1 = *(const __half2*)&r13;
        const __half2 d2 = *(const __half2*)&r14, d3 = *(const __half2*)&r15;

        s0 = __hadd2(s0, a0);  m0 = __hmax2(m0, a0);
        s1 = __hadd2(s1, a1);  m1 = __hmax2(m1, a1);
        s2 = __hadd2(s2, a2);  m2 = __hmax2(m2, a2);
        s3 = __hadd2(s3, a3);  m3 = __hmax2(m3, a3);
        s0 = __hadd2(s0, b0);  m0 = __hmax2(m0, b0);
        s1 = __hadd2(s1, b1);  m1 = __hmax2(m1, b1);
        s2 = __hadd2(s2, b2);  m2 = __hmax2(m2, b2);
        s3 = __hadd2(s3, b3);  m3 = __hmax2(m3, b3);
        s0 = __hadd2(s0, c0);  m0 = __hmax2(m0, c0);
        s1 = __hadd2(s1, c1);  m1 = __hmax2(m1, c1);
        s2 = __hadd2(s2, c2);  m2 = __hmax2(m2, c2);
        s3 = __hadd2(s3, c3);  m3 = __hmax2(m3, c3);
        s0 = __hadd2(s0, d0);  m0 = __hmax2(m0, d0);
        s1 = __hadd2(s1, d1);  m1 = __hmax2(m1, d1);
        s2 = __hadd2(s2, d2);  m2 = __hmax2(m2, d2);
        s3 = __hadd2(s3, d3);  m3 = __hmax2(m3, d3);
    }

    // Combine the 4 row-groups: lanes {p, p+8, p+16, p+24} hold same features.
    #pragma unroll
    for (int off = 8; off <= 16; off <<= 1) {
        s0 = __hadd2(s0, h2_shfl_xor(s0, off));
        s1 = __hadd2(s1, h2_shfl_xor(s1, off));
        s2 = __hadd2(s2, h2_shfl_xor(s2, off));
        s3 = __hadd2(s3, h2_shfl_xor(s3, off));
        m0 = __hmax2(m0, h2_shfl_xor(m0, off));
        m1 = __hmax2(m1, h2_shfl_xor(m1, off));
        m2 = __hmax2(m2, h2_shfl_xor(m2, off));
        m3 = __hmax2(m3, h2_shfl_xor(m3, off));
    }

    // Output row = 128 floats = 32 float4: [mean 16 float4 | max 16 float4].
    // Lane p holds features [8p, 8p+8). Lanes 0-7 write mean, 8-15 write max.
    const float inv = 1.0f / KNN;
    if (lane < 8) {
        float2 f0 = __half22float2(s0), f1 = __half22float2(s1);
        float2 f2 = __half22float2(s2), f3 = __half22float2(s3);
        float4 lo = make_float4(f0.x * inv, f0.y * inv, f1.x * inv, f1.y * inv);
        float4 hi = make_float4(f2.x * inv, f2.y * inv, f3.x * inv, f3.y * inv);
        out4[warp * 32 + 2 * p]     = lo;
        out4[warp * 32 + 2 * p + 1] = hi;
    } else if (lane < 16) {
        float2 f0 = __half22float2(m0), f1 = __half22float2(m1);
        float2 f2 = __half22float2(m2), f3 = __half22float2(m3);
        float4 lo = make_float4(f0.x, f0.y, f1.x, f1.y);
        float4 hi = make_float4(f2.x, f2.y, f3.x, f3.y);
        out4[warp * 32 + 16 + 2 * p]     = lo;
        out4[warp * 32 + 16 + 2 * p + 1] = hi;
    }
}

extern "C" void kernel_launch(void* const* d_in, const int* in_sizes, int n_in,
                              void* d_out, int out_size)
{
    const float4* x4   = (const float4*)d_in[0];  // x: [V, 64] float32
    const int*    idxs = (const int*)d_in[1];     // idxs: [V, 32] int32
    float4*       out4 = (float4*)d_out;          // out: [V, 128] float32

    const int V  = in_sizes[0] / FDIM;            // 100000
    const int n8 = in_sizes[0] / 8;               // V*F/8 (16B per thread)

    convert_kernel<<<(n8 + 255) / 256, 256>>>(x4, n8);

    const int warps_per_block = 256 / 32;         // 8
    const int blocks = (V + warps_per_block - 1) / warps_per_block;
    knn_mean_max_kernel<<<blocks, 256>>>(idxs, out4, V);
}